// round 15
// baseline (speedup 1.0000x reference)
#include <cuda_runtime.h>
#include <cstdint>

#define NN 100000
#define NP 100096          // 64-node padded
#define EE 1600000
#define GG 1000
#define IN_C 32
#define EDGE_C 16
#define DESCC 200
#define HH 64
#define LL 3
#define WPW 10             // 16-edge windows per warp

typedef unsigned long long ull;

// ---------------- device scratch ----------------
// Invariant: g_cnt, g_agg, g_pool, g_pcnt ZERO at kernel_launch entry
// (module-load zeros; nu3/readout restore zeros before graph end).
__device__ float g_h[NP * HH];
__device__ float g_hp[NP * HH];
__device__ float g_agg[NP * HH];
__device__ float g_cnt[NP];
__device__ float g_Wcomb[LL * EDGE_C * HH];
__device__ float g_WcombT[LL * HH * EDGE_C]; // [c][k], k-pairs adjacent
__device__ float g_bcomb[LL * HH];
__device__ float g_V1[LL * 2 * HH * HH];     // [umW1_top ; emW2@umW1_bot]
__device__ float g_bae[LL * HH];             // emb2 @ umW1_bot
__device__ float g_Whp[LL * HH * HH];        // umW2 @ emW1[l+1]_top
__device__ float g_bhp[LL * HH];             // umb2 @ emW1[l+1]_top
__device__ float g_Wi[IN_C * HH];            // node_W @ emW1[0]_top
__device__ float g_bi[HH];                   // node_b @ emW1[0]_top
__device__ float g_pool[GG * HH];
__device__ float g_pcnt[GG];
__device__ int g_ei64;
__device__ int g_b64;

// ---------------- f32x2 helpers ----------------
__device__ __forceinline__ ull pack2(float lo, float hi) {
    ull r;
    asm("mov.b64 %0, {%1, %2};" : "=l"(r) : "f"(lo), "f"(hi));
    return r;
}
__device__ __forceinline__ void unpack2(ull v, float& lo, float& hi) {
    asm("mov.b64 {%0, %1}, %2;" : "=f"(lo), "=f"(hi) : "l"(v));
}
__device__ __forceinline__ ull fma2(ull a, ull b, ull c) {
    ull d;
    asm("fma.rn.f32x2 %0, %1, %2, %3;" : "=l"(d) : "l"(a), "l"(b), "l"(c));
    return d;
}
__device__ __forceinline__ ull add2(ull a, ull b) {
    ull d;
    asm("add.rn.f32x2 %0, %1, %2;" : "=l"(d) : "l"(a), "l"(b));
    return d;
}

__device__ __forceinline__ long long load_idx(const void* p, long long i, int is64) {
    return is64 ? ((const long long*)p)[i] : (long long)((const int*)p)[i];
}

// ---------------- launch 0: prep = wcomb(b0-2) + compose(b3-5) + init-compose(b6)
__global__ __launch_bounds__(1024) void prep_kernel(const float* __restrict__ edge_W,
                                                    const float* __restrict__ edge_b,
                                                    const float* __restrict__ emW1,
                                                    const float* __restrict__ emb1,
                                                    const float* __restrict__ umW1,
                                                    const float* __restrict__ emW2,
                                                    const float* __restrict__ emb2,
                                                    const float* __restrict__ umW2,
                                                    const float* __restrict__ umb2,
                                                    const float* __restrict__ nW,
                                                    const float* __restrict__ nb) {
    __shared__ float smbuf[8192];
    const int tid = threadIdx.x;
    const int bid = blockIdx.x;
    if (bid <= 2) {
        float* sW1 = smbuf;
        float* sEW = smbuf + 4096;
        int l = bid;
        const float* W1l = emW1 + l * (2 * HH * HH) + HH * HH;
        for (int i = tid; i < HH * HH; i += 1024) sW1[i] = W1l[i];
        if (tid < EDGE_C * HH) sEW[tid] = edge_W[tid];
        __syncthreads();
        int k = tid >> 6, j = tid & 63;
        float acc = 0.f;
#pragma unroll 16
        for (int t = 0; t < HH; t++) acc += sEW[k * HH + t] * sW1[t * HH + j];
        g_Wcomb[l * EDGE_C * HH + k * HH + j] = acc;
        g_WcombT[l * HH * EDGE_C + j * EDGE_C + k] = acc;
        if (k == 0) {
            float accb = emb1[l * HH + j];
            for (int t = 0; t < HH; t++) accb += edge_b[t] * sW1[t * HH + j];
            g_bcomb[l * HH + j] = accb;
        }
    } else if (bid <= 5) {
        float* sA = smbuf;
        float* sB = smbuf + 4096;
        int l = bid - 3;
        for (int i = tid; i < 4096; i += 1024) {
            g_V1[l * 8192 + i] = umW1[l * 8192 + i];
            sA[i] = emW2[l * 4096 + i];
            sB[i] = umW1[l * 8192 + 4096 + i];
        }
        __syncthreads();
        for (int o = tid; o < 4096; o += 1024) {
            int r = o >> 6, c = o & 63;
            float s = 0.f;
#pragma unroll 16
            for (int t = 0; t < HH; t++) s += sA[r * 64 + t] * sB[t * 64 + c];
            g_V1[l * 8192 + 4096 + o] = s;
        }
        if (tid < 64) {
            float s = 0.f;
            for (int t = 0; t < HH; t++) s += emb2[l * 64 + t] * sB[t * 64 + tid];
            g_bae[l * 64 + tid] = s;
        }
        if (l + 1 < LL) {
            __syncthreads();
            for (int i = tid; i < 4096; i += 1024) {
                sA[i] = umW2[l * 4096 + i];
                sB[i] = emW1[(l + 1) * 8192 + i];
            }
            __syncthreads();
            for (int o = tid; o < 4096; o += 1024) {
                int r = o >> 6, c = o & 63;
                float s = 0.f;
#pragma unroll 16
                for (int t = 0; t < HH; t++) s += sA[r * 64 + t] * sB[t * 64 + c];
                g_Whp[l * 4096 + o] = s;
            }
            if (tid < 64) {
                float s = 0.f;
                for (int t = 0; t < HH; t++) s += umb2[l * 64 + t] * sB[t * 64 + tid];
                g_bhp[l * 64 + tid] = s;
            }
        }
    } else {
        float* sP = smbuf;
        float* sN = smbuf + 4096;
        for (int i = tid; i < HH * HH; i += 1024) sP[i] = emW1[i];
        for (int i = tid; i < IN_C * HH; i += 1024) sN[i] = nW[i];
        __syncthreads();
        for (int o = tid; o < IN_C * HH; o += 1024) {
            int r = o >> 6, c = o & 63;
            float s = 0.f;
#pragma unroll 16
            for (int t = 0; t < HH; t++) s += sN[r * 64 + t] * sP[t * 64 + c];
            g_Wi[o] = s;
        }
        if (tid < 64) {
            float s = 0.f;
            for (int t = 0; t < HH; t++) s += nb[t] * sP[t * 64 + tid];
            g_bi[tid] = s;
        }
    }
}

// ---------------- launch 1: node init (blocks 0..147) + detect/count (148..2195) ----------------
#define INIT_BLOCKS 148
#define CNT_BLOCKS 2048
__global__ __launch_bounds__(256) void initcount_kernel(const void* __restrict__ ei,
                                                        const void* __restrict__ batch,
                                                        const float* __restrict__ x,
                                                        const float* __restrict__ nW,
                                                        const float* __restrict__ nb) {
    __shared__ float sbuf[6272]; // sWh 2048 | sWp 2048 | sbx 128 | sx 2048
    const int tid = threadIdx.x;
    if (blockIdx.x >= INIT_BLOCKS) {
        __shared__ int s_is64;
        if (tid == 0) {
            const long long* p = (const long long*)ei;
            int ok = 1;
            for (int i = 1; i <= 16; i++) {
                long long v = p[EE - i];
                if (v < 0 || v >= NN) ok = 0;
            }
            s_is64 = ok;
            if (blockIdx.x == INIT_BLOCKS) {
                g_ei64 = ok;
                const long long* q = (const long long*)batch;
                int okb = 1;
                for (int i = 1; i <= 16; i++) {
                    long long v = q[NN / 2 - i];
                    if (v < 0 || v >= GG) okb = 0;
                }
                g_b64 = okb;
            }
        }
        __syncthreads();
        const int is64 = s_is64;
        int i = (blockIdx.x - INIT_BLOCKS) * 256 + tid;
        const int stride = CNT_BLOCKS * 256;
        for (; i < EE; i += stride) {
            long long dst = load_idx(ei, (long long)EE + i, is64);
            asm volatile("red.global.add.f32 [%0], %1;"
                         :: "l"(g_cnt + dst), "f"(1.0f) : "memory");
        }
        return;
    }
    float* sWh = sbuf;
    float* sWp = sbuf + 2048;
    float* sbx = sbuf + 4096;
    float* sx  = sbuf + 4224;
    for (int i = tid; i < IN_C * HH; i += 256) { sWh[i] = nW[i]; sWp[i] = g_Wi[i]; }
    if (tid < 64) { sbx[tid] = nb[tid]; sbx[64 + tid] = g_bi[tid]; }
    __syncthreads();
    const int w = tid >> 5, lane = tid & 31;
    const int nb8 = w * 8;
    const ull bh = *(const ull*)&sbx[2 * lane];
    const ull bp = *(const ull*)&sbx[64 + 2 * lane];
    for (int base = blockIdx.x * 64; base < NN; base += INIT_BLOCKS * 64) {
        for (int i = tid; i < 512; i += 256) {
            int node = base + (i >> 3);
            float4 v = make_float4(0.f, 0.f, 0.f, 0.f);
            if (node < NN) v = ((const float4*)x)[(long long)base * 8 + i];
            ((float4*)sx)[i] = v;
        }
        __syncthreads();
        ull ah[8], ap[8];
#pragma unroll
        for (int b = 0; b < 8; b++) { ah[b] = bh; ap[b] = bp; }
#pragma unroll
        for (int kq = 0; kq < 8; kq++) {
            const float* whr = &sWh[kq * 256 + 2 * lane];
            const float* wpr = &sWp[kq * 256 + 2 * lane];
            ull h0 = *(const ull*)(whr), h1 = *(const ull*)(whr + 64);
            ull h2 = *(const ull*)(whr + 128), h3 = *(const ull*)(whr + 192);
            ull p0 = *(const ull*)(wpr), p1 = *(const ull*)(wpr + 64);
            ull p2 = *(const ull*)(wpr + 128), p3 = *(const ull*)(wpr + 192);
#pragma unroll
            for (int b = 0; b < 8; b++) {
                float4 a = *(const float4*)&sx[(nb8 + b) * 32 + kq * 4];
                ull d;
                d = pack2(a.x, a.x); ah[b] = fma2(d, h0, ah[b]); ap[b] = fma2(d, p0, ap[b]);
                d = pack2(a.y, a.y); ah[b] = fma2(d, h1, ah[b]); ap[b] = fma2(d, p1, ap[b]);
                d = pack2(a.z, a.z); ah[b] = fma2(d, h2, ah[b]); ap[b] = fma2(d, p2, ap[b]);
                d = pack2(a.w, a.w); ah[b] = fma2(d, h3, ah[b]); ap[b] = fma2(d, p3, ap[b]);
            }
        }
#pragma unroll
        for (int b = 0; b < 8; b++) {
            int node = base + nb8 + b;
            if (node < NN) {
                *(ull*)&g_h[(long long)node * 64 + 2 * lane] = ah[b];
                *(ull*)&g_hp[(long long)node * 64 + 2 * lane] = ap[b];
            }
        }
        __syncthreads();
    }
}

// ---------------- launch 2: dummy (keeps edge7b at profiled index 3) ----------------
__global__ void dummy_kernel() {
    if (blockIdx.x == 0 && threadIdx.x < GG) g_pcnt[threadIdx.x] = 0.f; // idempotent
}

// ---------------- launch 3/5/7: edge7b — ea staged via cp.async (smem), hv via
// direct LDG.128 with 4-deep register prefetch pipeline, 16-lane RED.v4 ----------------
__device__ __forceinline__ void stage_ea(int slot, long long be, int s_n, int d_n,
                                         float* eaW, int2* sdW,
                                         const float* __restrict__ eattr, int lane) {
    const float* sp = eattr + be * EDGE_C + lane * 8;
    uint32_t dp = (uint32_t)__cvta_generic_to_shared(eaW + slot * 256 + lane * 8);
    asm volatile("cp.async.cg.shared.global [%0], [%1], 16;" :: "r"(dp), "l"(sp));
    asm volatile("cp.async.cg.shared.global [%0], [%1], 16;" :: "r"(dp + 16), "l"(sp + 4));
    if (lane < 16) sdW[slot * 16 + lane] = make_int2(s_n, d_n);
    asm volatile("cp.async.commit_group;");
}

__global__ __launch_bounds__(256) void edge7b_kernel(const void* __restrict__ ei,
                                                     const float* __restrict__ eattr, int l) {
    extern __shared__ float sedge[];
    // ea: 8w × 2 slots × 256 floats = 4096 floats (16 KB); sd: 8w × 32 int2 (2 KB)
    const int tid = threadIdx.x;
    const int w = tid >> 5, lane = tid & 31;
    const int g = lane >> 4, q = lane & 15;
    const int c0 = 4 * q;
    float* eaW = sedge + w * 512;
    int2* sdW = (int2*)(sedge + 4096) + w * 32;
    const int is64 = g_ei64;
    const float* wr = g_WcombT + l * (HH * EDGE_C) + c0 * EDGE_C;
    ull wk0[8], wk1[8], wk2[8], wk3[8];
#pragma unroll
    for (int tp = 0; tp < 8; tp++) {
        wk0[tp] = *(const ull*)(wr + 2 * tp);
        wk1[tp] = *(const ull*)(wr + EDGE_C + 2 * tp);
        wk2[tp] = *(const ull*)(wr + 2 * EDGE_C + 2 * tp);
        wk3[tp] = *(const ull*)(wr + 3 * EDGE_C + 2 * tp);
    }
    const ulonglong2 bb = *(const ulonglong2*)(g_bcomb + l * HH + c0);
    const long long wbase = (long long)(blockIdx.x * 8 + w) * (WPW * 16);

    // prologue: indices for windows 0,1; stage ea+sd for both
    int s0 = 0, d0 = 0, s1 = 0, d1 = 0;
    if (lane < 16) {
        s0 = (int)load_idx(ei, wbase + lane, is64);
        d0 = (int)load_idx(ei, (long long)EE + wbase + lane, is64);
        s1 = (int)load_idx(ei, wbase + 16 + lane, is64);
        d1 = (int)load_idx(ei, (long long)EE + wbase + 16 + lane, is64);
    }
    stage_ea(0, wbase, s0, d0, eaW, sdW, eattr, lane);
    stage_ea(1, wbase + 16, s1, d1, eaW, sdW, eattr, lane);
    __syncwarp();   // sd (plain STS) for windows 0,1 now visible

    // prime hv register pipeline: own-edges m=0..3 (all in window 0)
    int2 sdp[4];
    ulonglong2 hvp[4];
#pragma unroll
    for (int mp = 0; mp < 4; mp++) {
        int2 s = sdW[2 * mp + g];
        sdp[mp] = s;
        hvp[mp] = *(const ulonglong2*)(g_hp + (long long)s.x * HH + c0);
    }

#pragma unroll 1
    for (int k = 0; k < WPW; k++) {
        int sn = 0, dn = 0;
        const long long ben = wbase + (long long)(k + 2) * 16;
        if (k + 2 < WPW && lane < 16) {
            sn = (int)load_idx(ei, ben + lane, is64);
            dn = (int)load_idx(ei, (long long)EE + ben + lane, is64);
        }
        if (k < WPW - 1) { asm volatile("cp.async.wait_group 1;" ::: "memory"); }
        else             { asm volatile("cp.async.wait_group 0;" ::: "memory"); }
        __syncwarp();
        const int slot = k & 1;
        const float* eaS = eaW + slot * 256;
#pragma unroll
        for (int p = 0; p < 8; p++) {
            const int e = 2 * p + g;
            const int2 sd = sdp[p & 3];
            const ulonglong2 hv = hvp[p & 3];
            // prefetch own-edge m+4 (window k at p<4, window k+1 at p>=4; both staged)
            const int m4 = 8 * k + p + 4;
            if (m4 < 8 * WPW) {
                const int kk = m4 >> 3, pp = m4 & 7;
                int2 s = sdW[(kk & 1) * 16 + 2 * pp + g];
                sdp[p & 3] = s;
                hvp[p & 3] = *(const ulonglong2*)(g_hp + (long long)s.x * HH + c0);
            }
            const ulonglong2* ep = (const ulonglong2*)(eaS + e * 16);
            ull m0 = 0ull, m1 = 0ull, m2 = 0ull, m3 = 0ull;
#pragma unroll
            for (int t = 0; t < 4; t++) {
                ulonglong2 av = ep[t];               // LDS.128 broadcast
                m0 = fma2(av.x, wk0[2 * t], m0); m0 = fma2(av.y, wk0[2 * t + 1], m0);
                m1 = fma2(av.x, wk1[2 * t], m1); m1 = fma2(av.y, wk1[2 * t + 1], m1);
                m2 = fma2(av.x, wk2[2 * t], m2); m2 = fma2(av.y, wk2[2 * t + 1], m2);
                m3 = fma2(av.x, wk3[2 * t], m3); m3 = fma2(av.y, wk3[2 * t + 1], m3);
            }
            ull hb0 = add2(hv.x, bb.x);
            ull hb1 = add2(hv.y, bb.y);
            float h0, h1, h2, h3, a, b;
            unpack2(hb0, h0, h1);
            unpack2(hb1, h2, h3);
            float r0, r1, r2, r3;
            unpack2(m0, a, b); r0 = fmaxf(a + b + h0, 0.f);
            unpack2(m1, a, b); r1 = fmaxf(a + b + h1, 0.f);
            unpack2(m2, a, b); r2 = fmaxf(a + b + h2, 0.f);
            unpack2(m3, a, b); r3 = fmaxf(a + b + h3, 0.f);
            float* dp = g_agg + (long long)sd.y * HH + c0;
            asm volatile("red.global.add.v4.f32 [%0], {%1,%2,%3,%4};"
                         :: "l"(dp), "f"(r0), "f"(r1), "f"(r2), "f"(r3) : "memory");
        }
        if (k + 2 < WPW)
            stage_ea(slot, ben, sn, dn, eaW, sdW, eattr, lane);
    }
}
#define EDGE7B_SMEM (4096 * 4 + 8 * 32 * 8)   // 18432 B

// ---------------- launch 4/6/8: node update v3 (R9/R14 proven best) ----------------
#define NU3_SMEM_FLOATS (8192 + 4096 + 4096 + 4096 + 256)
__global__ __launch_bounds__(256, 2) void node_update3(const float* __restrict__ umb1,
                                                       const float* __restrict__ umW2,
                                                       const float* __restrict__ umb2,
                                                       const void* __restrict__ batch,
                                                       int l, int has_next) {
    extern __shared__ float sm[];
    float* sV1 = sm;
    float* sW2 = sV1 + 8192;
    float* sWhp = sW2 + 4096;
    float* sT  = sWhp + 4096;
    float* sB  = sT + 4096;
    const int tid = threadIdx.x;
    for (int i = tid; i < 8192; i += 256) sV1[i] = g_V1[l * 8192 + i];
    for (int i = tid; i < 4096; i += 256) sW2[i] = umW2[l * 4096 + i];
    if (has_next)
        for (int i = tid; i < 4096; i += 256) sWhp[i] = g_Whp[l * 4096 + i];
    if (tid < 64) {
        sB[tid] = umb1[l * 64 + tid];
        sB[64 + tid] = g_bae[l * 64 + tid];
        sB[128 + tid] = umb2[l * 64 + tid];
        sB[192 + tid] = has_next ? g_bhp[l * 64 + tid] : 0.f;
    }
    __syncthreads();
    const int isb64 = g_b64;
    const long long* b64p = (const long long*)batch;
    const int* b32p = (const int*)batch;
    const int w = tid >> 5, lane = tid & 31;
    float* sTw = sT + w * 512;
    const ull b12 = *(const ull*)&sB[2 * lane];
    const ull bae2 = *(const ull*)&sB[64 + 2 * lane];
    const ull b22 = *(const ull*)&sB[128 + 2 * lane];
    const ull bh2 = *(const ull*)&sB[192 + 2 * lane];

    for (int n0 = blockIdx.x * 64 + w * 8; n0 < NN; n0 += gridDim.x * 64) {
        const float* hb = g_h + (long long)n0 * 64;
        float* ab = g_agg + (long long)n0 * 64;
        ull acc[8];
#pragma unroll
        for (int b = 0; b < 8; b++) {
            float cn = g_cnt[n0 + b];
            acc[b] = fma2(pack2(cn, cn), bae2, b12);
        }
#pragma unroll 4
        for (int kq = 0; kq < 16; kq++) {
            const float* wr = &sV1[kq * 256 + 2 * lane];
            ull w0 = *(const ull*)(wr),        w1 = *(const ull*)(wr + 64);
            ull w2 = *(const ull*)(wr + 128),  w3 = *(const ull*)(wr + 192);
#pragma unroll
            for (int b = 0; b < 8; b++) {
                float4 a = *(const float4*)(hb + b * 64 + kq * 4);
                acc[b] = fma2(pack2(a.x, a.x), w0, acc[b]);
                acc[b] = fma2(pack2(a.y, a.y), w1, acc[b]);
                acc[b] = fma2(pack2(a.z, a.z), w2, acc[b]);
                acc[b] = fma2(pack2(a.w, a.w), w3, acc[b]);
            }
        }
#pragma unroll 4
        for (int kq = 0; kq < 16; kq++) {
            const float* wr = &sV1[(16 + kq) * 256 + 2 * lane];
            ull w0 = *(const ull*)(wr),        w1 = *(const ull*)(wr + 64);
            ull w2 = *(const ull*)(wr + 128),  w3 = *(const ull*)(wr + 192);
#pragma unroll
            for (int b = 0; b < 8; b++) {
                float4 a = *(const float4*)(ab + b * 64 + kq * 4);
                acc[b] = fma2(pack2(a.x, a.x), w0, acc[b]);
                acc[b] = fma2(pack2(a.y, a.y), w1, acc[b]);
                acc[b] = fma2(pack2(a.z, a.z), w2, acc[b]);
                acc[b] = fma2(pack2(a.w, a.w), w3, acc[b]);
            }
        }
#pragma unroll
        for (int b = 0; b < 8; b++) {
            float lo, hi;
            unpack2(acc[b], lo, hi);
            *(ull*)&sTw[b * 64 + 2 * lane] = pack2(fmaxf(lo, 0.f), fmaxf(hi, 0.f));
            *(ull*)(ab + b * 64 + 2 * lane) = 0ull;   // restore zero-invariant
        }
        __syncwarp();
        ull a2[8], a3[8];
#pragma unroll
        for (int b = 0; b < 8; b++) { a2[b] = b22; a3[b] = bh2; }
        if (has_next) {
#pragma unroll 2
            for (int kq = 0; kq < 16; kq++) {
                const float* w2r = &sW2[kq * 256 + 2 * lane];
                const float* whr = &sWhp[kq * 256 + 2 * lane];
                ull p0 = *(const ull*)(w2r), p1 = *(const ull*)(w2r + 64);
                ull p2 = *(const ull*)(w2r + 128), p3 = *(const ull*)(w2r + 192);
                ull q0 = *(const ull*)(whr), q1 = *(const ull*)(whr + 64);
                ull q2 = *(const ull*)(whr + 128), q3 = *(const ull*)(whr + 192);
#pragma unroll
                for (int b = 0; b < 8; b++) {
                    float4 a = *(const float4*)&sTw[b * 64 + kq * 4];
                    ull d;
                    d = pack2(a.x, a.x); a2[b] = fma2(d, p0, a2[b]); a3[b] = fma2(d, q0, a3[b]);
                    d = pack2(a.y, a.y); a2[b] = fma2(d, p1, a2[b]); a3[b] = fma2(d, q1, a3[b]);
                    d = pack2(a.z, a.z); a2[b] = fma2(d, p2, a2[b]); a3[b] = fma2(d, q2, a3[b]);
                    d = pack2(a.w, a.w); a2[b] = fma2(d, p3, a2[b]); a3[b] = fma2(d, q3, a3[b]);
                }
            }
#pragma unroll
            for (int b = 0; b < 8; b++) {
                *(ull*)&g_h[(long long)(n0 + b) * 64 + 2 * lane] = a2[b];
                *(ull*)&g_hp[(long long)(n0 + b) * 64 + 2 * lane] = a3[b];
            }
        } else {
#pragma unroll 2
            for (int kq = 0; kq < 16; kq++) {
                const float* w2r = &sW2[kq * 256 + 2 * lane];
                ull p0 = *(const ull*)(w2r), p1 = *(const ull*)(w2r + 64);
                ull p2 = *(const ull*)(w2r + 128), p3 = *(const ull*)(w2r + 192);
#pragma unroll
                for (int b = 0; b < 8; b++) {
                    float4 a = *(const float4*)&sTw[b * 64 + kq * 4];
                    a2[b] = fma2(pack2(a.x, a.x), p0, a2[b]);
                    a2[b] = fma2(pack2(a.y, a.y), p1, a2[b]);
                    a2[b] = fma2(pack2(a.z, a.z), p2, a2[b]);
                    a2[b] = fma2(pack2(a.w, a.w), p3, a2[b]);
                }
            }
#pragma unroll
            for (int b = 0; b < 8; b++) {
                int node = n0 + b;
                if (node < NN) {
                    long long bg = isb64 ? b64p[node] : (long long)b32p[node];
                    float lo, hi;
                    unpack2(a2[b], lo, hi);
                    float* dp = g_pool + bg * 64 + 2 * lane;
                    asm volatile("red.global.add.v2.f32 [%0], {%1,%2};"
                                 :: "l"(dp), "f"(lo), "f"(hi) : "memory");
                    if (lane == 0)
                        asm volatile("red.global.add.f32 [%0], %1;" :: "l"(g_pcnt + bg), "f"(1.0f) : "memory");
                }
            }
        }
        __syncwarp();
    }
}

// ---------------- launch 9: readout + cleanup ----------------
__global__ void readout_kernel(const float* __restrict__ desc,
                               const float* __restrict__ W1, const float* __restrict__ b1,
                               const float* __restrict__ W2, const float* __restrict__ b2,
                               float* __restrict__ out) {
    __shared__ float r[HH + DESCC];
    __shared__ float st[128];
    int g = blockIdx.x, tid = threadIdx.x;
    float cn = fmaxf(g_pcnt[g], 1.0f);
    for (int i = tid; i < HH; i += 128) r[i] = g_pool[g * HH + i] / cn;
    for (int i = tid; i < DESCC; i += 128) r[HH + i] = desc[(long long)g * DESCC + i];
    __syncthreads();
    if (tid < 64) g_pool[g * HH + tid] = 0.f;
    if (tid == 64) g_pcnt[g] = 0.f;
    for (int i = g * (NN / GG) + tid; i < (g + 1) * (NN / GG); i += 128) g_cnt[i] = 0.f;
    float acc = b1[tid];
#pragma unroll 8
    for (int k = 0; k < HH + DESCC; k++) acc += r[k] * W1[k * 128 + tid];
    acc = fmaxf(acc, 0.f);
    st[tid] = acc * W2[tid];
    __syncthreads();
    for (int s = 64; s > 0; s >>= 1) {
        if (tid < s) st[tid] += st[tid + s];
        __syncthreads();
    }
    if (tid == 0) out[g] = 1.0f / (1.0f + expf(-(st[0] + b2[0])));
}

// ---------------- launch ----------------
extern "C" void kernel_launch(void* const* d_in, const int* in_sizes, int n_in,
                              void* d_out, int out_size) {
    const float* x       = (const float*)d_in[0];
    const void*  ei      = d_in[1];
    const float* eattr   = (const float*)d_in[2];
    const void*  batch   = d_in[3];
    const float* desc    = (const float*)d_in[4];
    const float* node_W  = (const float*)d_in[5];
    const float* node_b  = (const float*)d_in[6];
    const float* edge_W  = (const float*)d_in[7];
    const float* edge_b  = (const float*)d_in[8];
    const float* emW1    = (const float*)d_in[9];
    const float* emb1    = (const float*)d_in[10];
    const float* emW2    = (const float*)d_in[11];
    const float* emb2    = (const float*)d_in[12];
    const float* umW1    = (const float*)d_in[13];
    const float* umb1    = (const float*)d_in[14];
    const float* umW2    = (const float*)d_in[15];
    const float* umb2    = (const float*)d_in[16];
    const float* roW1    = (const float*)d_in[17];
    const float* rob1    = (const float*)d_in[18];
    const float* roW2    = (const float*)d_in[19];
    const float* rob2    = (const float*)d_in[20];
    float* out = (float*)d_out;

    const int nu_smem = NU3_SMEM_FLOATS * (int)sizeof(float);
    cudaFuncSetAttribute(node_update3,
                         cudaFuncAttributeMaxDynamicSharedMemorySize, nu_smem);
    cudaFuncSetAttribute(edge7b_kernel,
                         cudaFuncAttributeMaxDynamicSharedMemorySize, EDGE7B_SMEM);

    prep_kernel<<<7, 1024>>>(edge_W, edge_b, emW1, emb1, umW1, emW2, emb2,      // 0
                             umW2, umb2, node_W, node_b);
    initcount_kernel<<<INIT_BLOCKS + CNT_BLOCKS, 256>>>(ei, batch, x,           // 1
                                                        node_W, node_b);
    dummy_kernel<<<1, 128>>>();                                                 // 2
    const int edge_blocks = EE / (WPW * 16 * 8);  // 1250
    for (int l = 0; l < LL; l++) {
        edge7b_kernel<<<edge_blocks, 256, EDGE7B_SMEM>>>(ei, eattr, l);         // 3,5,7
        node_update3<<<296, 256, nu_smem>>>(umb1, umW2, umb2, batch, l,         // 4,6,8
                                            l < LL - 1 ? 1 : 0);
    }
    readout_kernel<<<GG, 128>>>(desc, roW1, rob1, roW2, rob2, out);             // 9
}

// round 16
// speedup vs baseline: 1.0991x; 1.0991x over previous
#include <cuda_runtime.h>
#include <cstdint>

#define NN 100000
#define NP 100096          // 64-node padded
#define EE 1600000
#define GG 1000
#define IN_C 32
#define EDGE_C 16
#define DESCC 200
#define HH 64
#define LL 3
#define WPW 10             // 16-edge windows per warp

typedef unsigned long long ull;

// ---------------- device scratch ----------------
// Invariant: g_cnt, g_agg, g_pool, g_pcnt ZERO at kernel_launch entry
// (module-load zeros; nu3/readout restore zeros before graph end).
__device__ float g_h[NP * HH];
__device__ float g_hp[NP * HH];
__device__ float g_agg[NP * HH];
__device__ float g_cnt[NP];
__device__ float g_Wcomb[LL * EDGE_C * HH];
__device__ float g_WcombT[LL * HH * EDGE_C]; // [c][k], k-pairs adjacent
__device__ float g_bcomb[LL * HH];
__device__ float g_V1[LL * 2 * HH * HH];     // [umW1_top ; emW2@umW1_bot]
__device__ float g_bae[LL * HH];             // emb2 @ umW1_bot
__device__ float g_Whp[LL * HH * HH];        // umW2 @ emW1[l+1]_top
__device__ float g_bhp[LL * HH];             // umb2 @ emW1[l+1]_top
__device__ float g_Wi[IN_C * HH];            // node_W @ emW1[0]_top
__device__ float g_bi[HH];                   // node_b @ emW1[0]_top
__device__ float g_pool[GG * HH];
__device__ float g_pcnt[GG];
__device__ int g_ei64;
__device__ int g_b64;

// ---------------- f32x2 helpers ----------------
__device__ __forceinline__ ull pack2(float lo, float hi) {
    ull r;
    asm("mov.b64 %0, {%1, %2};" : "=l"(r) : "f"(lo), "f"(hi));
    return r;
}
__device__ __forceinline__ void unpack2(ull v, float& lo, float& hi) {
    asm("mov.b64 {%0, %1}, %2;" : "=f"(lo), "=f"(hi) : "l"(v));
}
__device__ __forceinline__ ull fma2(ull a, ull b, ull c) {
    ull d;
    asm("fma.rn.f32x2 %0, %1, %2, %3;" : "=l"(d) : "l"(a), "l"(b), "l"(c));
    return d;
}
__device__ __forceinline__ ull add2(ull a, ull b) {
    ull d;
    asm("add.rn.f32x2 %0, %1, %2;" : "=l"(d) : "l"(a), "l"(b));
    return d;
}

__device__ __forceinline__ long long load_idx(const void* p, long long i, int is64) {
    return is64 ? ((const long long*)p)[i] : (long long)((const int*)p)[i];
}

// ---------------- launch 0: prep = wcomb(b0-2) + compose(b3-5) + init-compose(b6)
__global__ __launch_bounds__(1024) void prep_kernel(const float* __restrict__ edge_W,
                                                    const float* __restrict__ edge_b,
                                                    const float* __restrict__ emW1,
                                                    const float* __restrict__ emb1,
                                                    const float* __restrict__ umW1,
                                                    const float* __restrict__ emW2,
                                                    const float* __restrict__ emb2,
                                                    const float* __restrict__ umW2,
                                                    const float* __restrict__ umb2,
                                                    const float* __restrict__ nW,
                                                    const float* __restrict__ nb) {
    __shared__ float smbuf[8192];
    const int tid = threadIdx.x;
    const int bid = blockIdx.x;
    if (bid <= 2) {
        float* sW1 = smbuf;
        float* sEW = smbuf + 4096;
        int l = bid;
        const float* W1l = emW1 + l * (2 * HH * HH) + HH * HH;
        for (int i = tid; i < HH * HH; i += 1024) sW1[i] = W1l[i];
        if (tid < EDGE_C * HH) sEW[tid] = edge_W[tid];
        __syncthreads();
        int k = tid >> 6, j = tid & 63;
        float acc = 0.f;
#pragma unroll 16
        for (int t = 0; t < HH; t++) acc += sEW[k * HH + t] * sW1[t * HH + j];
        g_Wcomb[l * EDGE_C * HH + k * HH + j] = acc;
        g_WcombT[l * HH * EDGE_C + j * EDGE_C + k] = acc;
        if (k == 0) {
            float accb = emb1[l * HH + j];
            for (int t = 0; t < HH; t++) accb += edge_b[t] * sW1[t * HH + j];
            g_bcomb[l * HH + j] = accb;
        }
    } else if (bid <= 5) {
        float* sA = smbuf;
        float* sB = smbuf + 4096;
        int l = bid - 3;
        for (int i = tid; i < 4096; i += 1024) {
            g_V1[l * 8192 + i] = umW1[l * 8192 + i];
            sA[i] = emW2[l * 4096 + i];
            sB[i] = umW1[l * 8192 + 4096 + i];
        }
        __syncthreads();
        for (int o = tid; o < 4096; o += 1024) {
            int r = o >> 6, c = o & 63;
            float s = 0.f;
#pragma unroll 16
            for (int t = 0; t < HH; t++) s += sA[r * 64 + t] * sB[t * 64 + c];
            g_V1[l * 8192 + 4096 + o] = s;
        }
        if (tid < 64) {
            float s = 0.f;
            for (int t = 0; t < HH; t++) s += emb2[l * 64 + t] * sB[t * 64 + tid];
            g_bae[l * 64 + tid] = s;
        }
        if (l + 1 < LL) {
            __syncthreads();
            for (int i = tid; i < 4096; i += 1024) {
                sA[i] = umW2[l * 4096 + i];
                sB[i] = emW1[(l + 1) * 8192 + i];
            }
            __syncthreads();
            for (int o = tid; o < 4096; o += 1024) {
                int r = o >> 6, c = o & 63;
                float s = 0.f;
#pragma unroll 16
                for (int t = 0; t < HH; t++) s += sA[r * 64 + t] * sB[t * 64 + c];
                g_Whp[l * 4096 + o] = s;
            }
            if (tid < 64) {
                float s = 0.f;
                for (int t = 0; t < HH; t++) s += umb2[l * 64 + t] * sB[t * 64 + tid];
                g_bhp[l * 64 + tid] = s;
            }
        }
    } else {
        float* sP = smbuf;
        float* sN = smbuf + 4096;
        for (int i = tid; i < HH * HH; i += 1024) sP[i] = emW1[i];
        for (int i = tid; i < IN_C * HH; i += 1024) sN[i] = nW[i];
        __syncthreads();
        for (int o = tid; o < IN_C * HH; o += 1024) {
            int r = o >> 6, c = o & 63;
            float s = 0.f;
#pragma unroll 16
            for (int t = 0; t < HH; t++) s += sN[r * 64 + t] * sP[t * 64 + c];
            g_Wi[o] = s;
        }
        if (tid < 64) {
            float s = 0.f;
            for (int t = 0; t < HH; t++) s += nb[t] * sP[t * 64 + tid];
            g_bi[tid] = s;
        }
    }
}

// ---------------- launch 1: node init (blocks 0..147) + detect/count (148..2195) ----------------
#define INIT_BLOCKS 148
#define CNT_BLOCKS 2048
__global__ __launch_bounds__(256) void initcount_kernel(const void* __restrict__ ei,
                                                        const void* __restrict__ batch,
                                                        const float* __restrict__ x,
                                                        const float* __restrict__ nW,
                                                        const float* __restrict__ nb) {
    __shared__ float sbuf[6272]; // sWh 2048 | sWp 2048 | sbx 128 | sx 2048
    const int tid = threadIdx.x;
    if (blockIdx.x >= INIT_BLOCKS) {
        __shared__ int s_is64;
        if (tid == 0) {
            const long long* p = (const long long*)ei;
            int ok = 1;
            for (int i = 1; i <= 16; i++) {
                long long v = p[EE - i];
                if (v < 0 || v >= NN) ok = 0;
            }
            s_is64 = ok;
            if (blockIdx.x == INIT_BLOCKS) {
                g_ei64 = ok;
                const long long* q = (const long long*)batch;
                int okb = 1;
                for (int i = 1; i <= 16; i++) {
                    long long v = q[NN / 2 - i];
                    if (v < 0 || v >= GG) okb = 0;
                }
                g_b64 = okb;
            }
        }
        __syncthreads();
        const int is64 = s_is64;
        int i = (blockIdx.x - INIT_BLOCKS) * 256 + tid;
        const int stride = CNT_BLOCKS * 256;
        for (; i < EE; i += stride) {
            long long dst = load_idx(ei, (long long)EE + i, is64);
            asm volatile("red.global.add.f32 [%0], %1;"
                         :: "l"(g_cnt + dst), "f"(1.0f) : "memory");
        }
        return;
    }
    float* sWh = sbuf;
    float* sWp = sbuf + 2048;
    float* sbx = sbuf + 4096;
    float* sx  = sbuf + 4224;
    for (int i = tid; i < IN_C * HH; i += 256) { sWh[i] = nW[i]; sWp[i] = g_Wi[i]; }
    if (tid < 64) { sbx[tid] = nb[tid]; sbx[64 + tid] = g_bi[tid]; }
    __syncthreads();
    const int w = tid >> 5, lane = tid & 31;
    const int nb8 = w * 8;
    const ull bh = *(const ull*)&sbx[2 * lane];
    const ull bp = *(const ull*)&sbx[64 + 2 * lane];
    for (int base = blockIdx.x * 64; base < NN; base += INIT_BLOCKS * 64) {
        for (int i = tid; i < 512; i += 256) {
            int node = base + (i >> 3);
            float4 v = make_float4(0.f, 0.f, 0.f, 0.f);
            if (node < NN) v = ((const float4*)x)[(long long)base * 8 + i];
            ((float4*)sx)[i] = v;
        }
        __syncthreads();
        ull ah[8], ap[8];
#pragma unroll
        for (int b = 0; b < 8; b++) { ah[b] = bh; ap[b] = bp; }
#pragma unroll
        for (int kq = 0; kq < 8; kq++) {
            const float* whr = &sWh[kq * 256 + 2 * lane];
            const float* wpr = &sWp[kq * 256 + 2 * lane];
            ull h0 = *(const ull*)(whr), h1 = *(const ull*)(whr + 64);
            ull h2 = *(const ull*)(whr + 128), h3 = *(const ull*)(whr + 192);
            ull p0 = *(const ull*)(wpr), p1 = *(const ull*)(wpr + 64);
            ull p2 = *(const ull*)(wpr + 128), p3 = *(const ull*)(wpr + 192);
#pragma unroll
            for (int b = 0; b < 8; b++) {
                float4 a = *(const float4*)&sx[(nb8 + b) * 32 + kq * 4];
                ull d;
                d = pack2(a.x, a.x); ah[b] = fma2(d, h0, ah[b]); ap[b] = fma2(d, p0, ap[b]);
                d = pack2(a.y, a.y); ah[b] = fma2(d, h1, ah[b]); ap[b] = fma2(d, p1, ap[b]);
                d = pack2(a.z, a.z); ah[b] = fma2(d, h2, ah[b]); ap[b] = fma2(d, p2, ap[b]);
                d = pack2(a.w, a.w); ah[b] = fma2(d, h3, ah[b]); ap[b] = fma2(d, p3, ap[b]);
            }
        }
#pragma unroll
        for (int b = 0; b < 8; b++) {
            int node = base + nb8 + b;
            if (node < NN) {
                *(ull*)&g_h[(long long)node * 64 + 2 * lane] = ah[b];
                *(ull*)&g_hp[(long long)node * 64 + 2 * lane] = ap[b];
            }
        }
        __syncthreads();
    }
}

// ---------------- launch 2: dummy (keeps edge7b at profiled index 3) ----------------
__global__ void dummy_kernel() {
    if (blockIdx.x == 0 && threadIdx.x < GG) g_pcnt[threadIdx.x] = 0.f; // idempotent
}

// ---------------- launch 3/5/7: edge7b — ea staged via cp.async (smem), hv via
// direct LDG.128 register pipeline; capped at 128 regs -> 2 blocks/SM ----------------
__device__ __forceinline__ void stage_ea(int slot, long long be, int s_n, int d_n,
                                         float* eaW, int2* sdW,
                                         const float* __restrict__ eattr, int lane) {
    const float* sp = eattr + be * EDGE_C + lane * 8;
    uint32_t dp = (uint32_t)__cvta_generic_to_shared(eaW + slot * 256 + lane * 8);
    asm volatile("cp.async.cg.shared.global [%0], [%1], 16;" :: "r"(dp), "l"(sp));
    asm volatile("cp.async.cg.shared.global [%0], [%1], 16;" :: "r"(dp + 16), "l"(sp + 4));
    if (lane < 16) sdW[slot * 16 + lane] = make_int2(s_n, d_n);
    asm volatile("cp.async.commit_group;");
}

__global__ __launch_bounds__(256, 2) void edge7b_kernel(const void* __restrict__ ei,
                                                        const float* __restrict__ eattr, int l) {
    extern __shared__ float sedge[];
    // ea: 8w × 2 slots × 256 floats = 4096 floats (16 KB); sd: 8w × 32 int2 (2 KB)
    const int tid = threadIdx.x;
    const int w = tid >> 5, lane = tid & 31;
    const int g = lane >> 4, q = lane & 15;
    const int c0 = 4 * q;
    float* eaW = sedge + w * 512;
    int2* sdW = (int2*)(sedge + 4096) + w * 32;
    const int is64 = g_ei64;
    const float* wr = g_WcombT + l * (HH * EDGE_C) + c0 * EDGE_C;
    ull wk0[8], wk1[8], wk2[8], wk3[8];
#pragma unroll
    for (int tp = 0; tp < 8; tp++) {
        wk0[tp] = *(const ull*)(wr + 2 * tp);
        wk1[tp] = *(const ull*)(wr + EDGE_C + 2 * tp);
        wk2[tp] = *(const ull*)(wr + 2 * EDGE_C + 2 * tp);
        wk3[tp] = *(const ull*)(wr + 3 * EDGE_C + 2 * tp);
    }
    const ulonglong2 bb = *(const ulonglong2*)(g_bcomb + l * HH + c0);
    const long long wbase = (long long)(blockIdx.x * 8 + w) * (WPW * 16);

    // prologue: indices for windows 0,1; stage ea+sd for both
    int s0 = 0, d0 = 0, s1 = 0, d1 = 0;
    if (lane < 16) {
        s0 = (int)load_idx(ei, wbase + lane, is64);
        d0 = (int)load_idx(ei, (long long)EE + wbase + lane, is64);
        s1 = (int)load_idx(ei, wbase + 16 + lane, is64);
        d1 = (int)load_idx(ei, (long long)EE + wbase + 16 + lane, is64);
    }
    stage_ea(0, wbase, s0, d0, eaW, sdW, eattr, lane);
    stage_ea(1, wbase + 16, s1, d1, eaW, sdW, eattr, lane);
    __syncwarp();   // sd (plain STS) for windows 0,1 now visible

    // prime hv register pipeline: own-edges m=0..3 (all in window 0)
    int2 sdp[4];
    ulonglong2 hvp[4];
#pragma unroll
    for (int mp = 0; mp < 4; mp++) {
        int2 s = sdW[2 * mp + g];
        sdp[mp] = s;
        hvp[mp] = *(const ulonglong2*)(g_hp + (long long)s.x * HH + c0);
    }

#pragma unroll 1
    for (int k = 0; k < WPW; k++) {
        int sn = 0, dn = 0;
        const long long ben = wbase + (long long)(k + 2) * 16;
        if (k + 2 < WPW && lane < 16) {
            sn = (int)load_idx(ei, ben + lane, is64);
            dn = (int)load_idx(ei, (long long)EE + ben + lane, is64);
        }
        if (k < WPW - 1) { asm volatile("cp.async.wait_group 1;" ::: "memory"); }
        else             { asm volatile("cp.async.wait_group 0;" ::: "memory"); }
        __syncwarp();
        const int slot = k & 1;
        const float* eaS = eaW + slot * 256;
#pragma unroll
        for (int p = 0; p < 8; p++) {
            const int e = 2 * p + g;
            const int2 sd = sdp[p & 3];
            const ulonglong2 hv = hvp[p & 3];
            // prefetch own-edge m+4 (window k at p<4, window k+1 at p>=4; both staged)
            const int m4 = 8 * k + p + 4;
            if (m4 < 8 * WPW) {
                const int kk = m4 >> 3, pp = m4 & 7;
                int2 s = sdW[(kk & 1) * 16 + 2 * pp + g];
                sdp[p & 3] = s;
                hvp[p & 3] = *(const ulonglong2*)(g_hp + (long long)s.x * HH + c0);
            }
            const ulonglong2* ep = (const ulonglong2*)(eaS + e * 16);
            ull m0 = 0ull, m1 = 0ull, m2 = 0ull, m3 = 0ull;
#pragma unroll
            for (int t = 0; t < 4; t++) {
                ulonglong2 av = ep[t];               // LDS.128 broadcast
                m0 = fma2(av.x, wk0[2 * t], m0); m0 = fma2(av.y, wk0[2 * t + 1], m0);
                m1 = fma2(av.x, wk1[2 * t], m1); m1 = fma2(av.y, wk1[2 * t + 1], m1);
                m2 = fma2(av.x, wk2[2 * t], m2); m2 = fma2(av.y, wk2[2 * t + 1], m2);
                m3 = fma2(av.x, wk3[2 * t], m3); m3 = fma2(av.y, wk3[2 * t + 1], m3);
            }
            ull hb0 = add2(hv.x, bb.x);
            ull hb1 = add2(hv.y, bb.y);
            float h0, h1, h2, h3, a, b;
            unpack2(hb0, h0, h1);
            unpack2(hb1, h2, h3);
            float r0, r1, r2, r3;
            unpack2(m0, a, b); r0 = fmaxf(a + b + h0, 0.f);
            unpack2(m1, a, b); r1 = fmaxf(a + b + h1, 0.f);
            unpack2(m2, a, b); r2 = fmaxf(a + b + h2, 0.f);
            unpack2(m3, a, b); r3 = fmaxf(a + b + h3, 0.f);
            float* dp = g_agg + (long long)sd.y * HH + c0;
            asm volatile("red.global.add.v4.f32 [%0], {%1,%2,%3,%4};"
                         :: "l"(dp), "f"(r0), "f"(r1), "f"(r2), "f"(r3) : "memory");
        }
        if (k + 2 < WPW)
            stage_ea(slot, ben, sn, dn, eaW, sdW, eattr, lane);
    }
}
#define EDGE7B_SMEM (4096 * 4 + 8 * 32 * 8)   // 18432 B

// ---------------- launch 4/6/8: node update v3 (R9/R14 proven best) ----------------
#define NU3_SMEM_FLOATS (8192 + 4096 + 4096 + 4096 + 256)
__global__ __launch_bounds__(256, 2) void node_update3(const float* __restrict__ umb1,
                                                       const float* __restrict__ umW2,
                                                       const float* __restrict__ umb2,
                                                       const void* __restrict__ batch,
                                                       int l, int has_next) {
    extern __shared__ float sm[];
    float* sV1 = sm;
    float* sW2 = sV1 + 8192;
    float* sWhp = sW2 + 4096;
    float* sT  = sWhp + 4096;
    float* sB  = sT + 4096;
    const int tid = threadIdx.x;
    for (int i = tid; i < 8192; i += 256) sV1[i] = g_V1[l * 8192 + i];
    for (int i = tid; i < 4096; i += 256) sW2[i] = umW2[l * 4096 + i];
    if (has_next)
        for (int i = tid; i < 4096; i += 256) sWhp[i] = g_Whp[l * 4096 + i];
    if (tid < 64) {
        sB[tid] = umb1[l * 64 + tid];
        sB[64 + tid] = g_bae[l * 64 + tid];
        sB[128 + tid] = umb2[l * 64 + tid];
        sB[192 + tid] = has_next ? g_bhp[l * 64 + tid] : 0.f;
    }
    __syncthreads();
    const int isb64 = g_b64;
    const long long* b64p = (const long long*)batch;
    const int* b32p = (const int*)batch;
    const int w = tid >> 5, lane = tid & 31;
    float* sTw = sT + w * 512;
    const ull b12 = *(const ull*)&sB[2 * lane];
    const ull bae2 = *(const ull*)&sB[64 + 2 * lane];
    const ull b22 = *(const ull*)&sB[128 + 2 * lane];
    const ull bh2 = *(const ull*)&sB[192 + 2 * lane];

    for (int n0 = blockIdx.x * 64 + w * 8; n0 < NN; n0 += gridDim.x * 64) {
        const float* hb = g_h + (long long)n0 * 64;
        float* ab = g_agg + (long long)n0 * 64;
        ull acc[8];
#pragma unroll
        for (int b = 0; b < 8; b++) {
            float cn = g_cnt[n0 + b];
            acc[b] = fma2(pack2(cn, cn), bae2, b12);
        }
#pragma unroll 4
        for (int kq = 0; kq < 16; kq++) {
            const float* wr = &sV1[kq * 256 + 2 * lane];
            ull w0 = *(const ull*)(wr),        w1 = *(const ull*)(wr + 64);
            ull w2 = *(const ull*)(wr + 128),  w3 = *(const ull*)(wr + 192);
#pragma unroll
            for (int b = 0; b < 8; b++) {
                float4 a = *(const float4*)(hb + b * 64 + kq * 4);
                acc[b] = fma2(pack2(a.x, a.x), w0, acc[b]);
                acc[b] = fma2(pack2(a.y, a.y), w1, acc[b]);
                acc[b] = fma2(pack2(a.z, a.z), w2, acc[b]);
                acc[b] = fma2(pack2(a.w, a.w), w3, acc[b]);
            }
        }
#pragma unroll 4
        for (int kq = 0; kq < 16; kq++) {
            const float* wr = &sV1[(16 + kq) * 256 + 2 * lane];
            ull w0 = *(const ull*)(wr),        w1 = *(const ull*)(wr + 64);
            ull w2 = *(const ull*)(wr + 128),  w3 = *(const ull*)(wr + 192);
#pragma unroll
            for (int b = 0; b < 8; b++) {
                float4 a = *(const float4*)(ab + b * 64 + kq * 4);
                acc[b] = fma2(pack2(a.x, a.x), w0, acc[b]);
                acc[b] = fma2(pack2(a.y, a.y), w1, acc[b]);
                acc[b] = fma2(pack2(a.z, a.z), w2, acc[b]);
                acc[b] = fma2(pack2(a.w, a.w), w3, acc[b]);
            }
        }
#pragma unroll
        for (int b = 0; b < 8; b++) {
            float lo, hi;
            unpack2(acc[b], lo, hi);
            *(ull*)&sTw[b * 64 + 2 * lane] = pack2(fmaxf(lo, 0.f), fmaxf(hi, 0.f));
            *(ull*)(ab + b * 64 + 2 * lane) = 0ull;   // restore zero-invariant
        }
        __syncwarp();
        ull a2[8], a3[8];
#pragma unroll
        for (int b = 0; b < 8; b++) { a2[b] = b22; a3[b] = bh2; }
        if (has_next) {
#pragma unroll 2
            for (int kq = 0; kq < 16; kq++) {
                const float* w2r = &sW2[kq * 256 + 2 * lane];
                const float* whr = &sWhp[kq * 256 + 2 * lane];
                ull p0 = *(const ull*)(w2r), p1 = *(const ull*)(w2r + 64);
                ull p2 = *(const ull*)(w2r + 128), p3 = *(const ull*)(w2r + 192);
                ull q0 = *(const ull*)(whr), q1 = *(const ull*)(whr + 64);
                ull q2 = *(const ull*)(whr + 128), q3 = *(const ull*)(whr + 192);
#pragma unroll
                for (int b = 0; b < 8; b++) {
                    float4 a = *(const float4*)&sTw[b * 64 + kq * 4];
                    ull d;
                    d = pack2(a.x, a.x); a2[b] = fma2(d, p0, a2[b]); a3[b] = fma2(d, q0, a3[b]);
                    d = pack2(a.y, a.y); a2[b] = fma2(d, p1, a2[b]); a3[b] = fma2(d, q1, a3[b]);
                    d = pack2(a.z, a.z); a2[b] = fma2(d, p2, a2[b]); a3[b] = fma2(d, q2, a3[b]);
                    d = pack2(a.w, a.w); a2[b] = fma2(d, p3, a2[b]); a3[b] = fma2(d, q3, a3[b]);
                }
            }
#pragma unroll
            for (int b = 0; b < 8; b++) {
                *(ull*)&g_h[(long long)(n0 + b) * 64 + 2 * lane] = a2[b];
                *(ull*)&g_hp[(long long)(n0 + b) * 64 + 2 * lane] = a3[b];
            }
        } else {
#pragma unroll 2
            for (int kq = 0; kq < 16; kq++) {
                const float* w2r = &sW2[kq * 256 + 2 * lane];
                ull p0 = *(const ull*)(w2r), p1 = *(const ull*)(w2r + 64);
                ull p2 = *(const ull*)(w2r + 128), p3 = *(const ull*)(w2r + 192);
#pragma unroll
                for (int b = 0; b < 8; b++) {
                    float4 a = *(const float4*)&sTw[b * 64 + kq * 4];
                    a2[b] = fma2(pack2(a.x, a.x), p0, a2[b]);
                    a2[b] = fma2(pack2(a.y, a.y), p1, a2[b]);
                    a2[b] = fma2(pack2(a.z, a.z), p2, a2[b]);
                    a2[b] = fma2(pack2(a.w, a.w), p3, a2[b]);
                }
            }
#pragma unroll
            for (int b = 0; b < 8; b++) {
                int node = n0 + b;
                if (node < NN) {
                    long long bg = isb64 ? b64p[node] : (long long)b32p[node];
                    float lo, hi;
                    unpack2(a2[b], lo, hi);
                    float* dp = g_pool + bg * 64 + 2 * lane;
                    asm volatile("red.global.add.v2.f32 [%0], {%1,%2};"
                                 :: "l"(dp), "f"(lo), "f"(hi) : "memory");
                    if (lane == 0)
                        asm volatile("red.global.add.f32 [%0], %1;" :: "l"(g_pcnt + bg), "f"(1.0f) : "memory");
                }
            }
        }
        __syncwarp();
    }
}

// ---------------- launch 9: readout + cleanup ----------------
__global__ void readout_kernel(const float* __restrict__ desc,
                               const float* __restrict__ W1, const float* __restrict__ b1,
                               const float* __restrict__ W2, const float* __restrict__ b2,
                               float* __restrict__ out) {
    __shared__ float r[HH + DESCC];
    __shared__ float st[128];
    int g = blockIdx.x, tid = threadIdx.x;
    float cn = fmaxf(g_pcnt[g], 1.0f);
    for (int i = tid; i < HH; i += 128) r[i] = g_pool[g * HH + i] / cn;
    for (int i = tid; i < DESCC; i += 128) r[HH + i] = desc[(long long)g * DESCC + i];
    __syncthreads();
    if (tid < 64) g_pool[g * HH + tid] = 0.f;
    if (tid == 64) g_pcnt[g] = 0.f;
    for (int i = g * (NN / GG) + tid; i < (g + 1) * (NN / GG); i += 128) g_cnt[i] = 0.f;
    float acc = b1[tid];
#pragma unroll 8
    for (int k = 0; k < HH + DESCC; k++) acc += r[k] * W1[k * 128 + tid];
    acc = fmaxf(acc, 0.f);
    st[tid] = acc * W2[tid];
    __syncthreads();
    for (int s = 64; s > 0; s >>= 1) {
        if (tid < s) st[tid] += st[tid + s];
        __syncthreads();
    }
    if (tid == 0) out[g] = 1.0f / (1.0f + expf(-(st[0] + b2[0])));
}

// ---------------- launch ----------------
extern "C" void kernel_launch(void* const* d_in, const int* in_sizes, int n_in,
                              void* d_out, int out_size) {
    const float* x       = (const float*)d_in[0];
    const void*  ei      = d_in[1];
    const float* eattr   = (const float*)d_in[2];
    const void*  batch   = d_in[3];
    const float* desc    = (const float*)d_in[4];
    const float* node_W  = (const float*)d_in[5];
    const float* node_b  = (const float*)d_in[6];
    const float* edge_W  = (const float*)d_in[7];
    const float* edge_b  = (const float*)d_in[8];
    const float* emW1    = (const float*)d_in[9];
    const float* emb1    = (const float*)d_in[10];
    const float* emW2    = (const float*)d_in[11];
    const float* emb2    = (const float*)d_in[12];
    const float* umW1    = (const float*)d_in[13];
    const float* umb1    = (const float*)d_in[14];
    const float* umW2    = (const float*)d_in[15];
    const float* umb2    = (const float*)d_in[16];
    const float* roW1    = (const float*)d_in[17];
    const float* rob1    = (const float*)d_in[18];
    const float* roW2    = (const float*)d_in[19];
    const float* rob2    = (const float*)d_in[20];
    float* out = (float*)d_out;

    const int nu_smem = NU3_SMEM_FLOATS * (int)sizeof(float);
    cudaFuncSetAttribute(node_update3,
                         cudaFuncAttributeMaxDynamicSharedMemorySize, nu_smem);
    cudaFuncSetAttribute(edge7b_kernel,
                         cudaFuncAttributeMaxDynamicSharedMemorySize, EDGE7B_SMEM);

    prep_kernel<<<7, 1024>>>(edge_W, edge_b, emW1, emb1, umW1, emW2, emb2,      // 0
                             umW2, umb2, node_W, node_b);
    initcount_kernel<<<INIT_BLOCKS + CNT_BLOCKS, 256>>>(ei, batch, x,           // 1
                                                        node_W, node_b);
    dummy_kernel<<<1, 128>>>();                                                 // 2
    const int edge_blocks = EE / (WPW * 16 * 8);  // 1250
    for (int l = 0; l < LL; l++) {
        edge7b_kernel<<<edge_blocks, 256, EDGE7B_SMEM>>>(ei, eattr, l);         // 3,5,7
        node_update3<<<296, 256, nu_smem>>>(umb1, umW2, umb2, batch, l,         // 4,6,8
                                            l < LL - 1 ? 1 : 0);
    }
    readout_kernel<<<GG, 128>>>(desc, roW1, rob1, roW2, rob2, out);             // 9
}